// round 8
// baseline (speedup 1.0000x reference)
#include <cuda_runtime.h>
#include <cuda_bf16.h>
#include <cstdint>

// SwitchingLinear: out[b,:] = W[idx[b]] @ x[b]
// B=2048, C=64, IN=OUT=512 fp32.
// ONE fused kernel, warp-specialized producer/consumer, 4-deep 16KB ring,
// sized for 3 CTAs/SM (TN=64, <=85 regs): 24 warps/SM to hide DRAM latency.
//   warps 4-7: producers (LDG fp32 -> split-bf16 cvt -> STS)
//   warps 0-3: consumers (LDSM -> HMMA fp32 accum), 16-row M-skip
// Split-bf16: v = hi + lo;  D = Ah*Bh + Ah*Bl + Al*Bh.
// Grid = (expert, n-block 64): 512 CTAs, zero dead blocks.

#define BB    2048
#define CC    64
#define KIN   512
#define NOUT  512
#define TM    64
#define TN    64
#define KB    32
#define NCH   (KIN / KB)     // 16
#define NSTG  4
#define STGB  16384          // Ah 4K | Al 4K | Bh 4K | Bl 4K
#define RING_OFF 1024
#define SMEM_DYN (RING_OFF + NSTG * STGB)   // 66560

__device__ __forceinline__ uint32_t smem_u32(const void* p) {
    uint32_t a;
    asm("{ .reg .u64 t; cvta.to.shared.u64 t, %1; cvt.u32.u64 %0, t; }"
        : "=r"(a) : "l"(p));
    return a;
}

#define SW64(o) ((o) ^ (((o) >> 3) & 0x30))

#define BAR_SYNC(id)   asm volatile("bar.sync %0, 256;"   :: "r"(id) : "memory")
#define BAR_ARRIVE(id) asm volatile("bar.arrive %0, 256;" :: "r"(id) : "memory")

#define LDSM4(r0, r1, r2, r3, a)                                             \
    asm volatile("ldmatrix.sync.aligned.m8n8.x4.shared.b16 {%0,%1,%2,%3}, [%4];" \
                 : "=r"(r0), "=r"(r1), "=r"(r2), "=r"(r3) : "r"(a))

#define MMA(d, a, b0, b1)                                                    \
    asm volatile("mma.sync.aligned.m16n8k16.row.col.f32.bf16.bf16.f32 "      \
                 "{%0,%1,%2,%3},{%4,%5,%6,%7},{%8,%9},{%0,%1,%2,%3};"        \
                 : "+f"((d)[0]), "+f"((d)[1]), "+f"((d)[2]), "+f"((d)[3])    \
                 : "r"((a)[0]), "r"((a)[1]), "r"((a)[2]), "r"((a)[3]),       \
                   "r"(b0), "r"(b1))

// Split fp32 pair -> bf16x2 hi + bf16x2 lo (lo = v - float(hi)).
__device__ __forceinline__ void cvt2(float f0, float f1, uint32_t& h, uint32_t& l) {
    asm("cvt.rn.bf16x2.f32 %0, %1, %2;" : "=r"(h) : "f"(f1), "f"(f0));
    float h0 = __uint_as_float(h << 16);
    float h1 = __uint_as_float(h & 0xFFFF0000u);
    float l0 = f0 - h0, l1 = f1 - h1;
    asm("cvt.rn.bf16x2.f32 %0, %1, %2;" : "=r"(l) : "f"(l1), "f"(l0));
}

__device__ __forceinline__ void cvt_sts(const float4& v, char* hp, char* lp) {
    uint32_t h0, l0, h1, l1;
    cvt2(v.x, v.y, h0, l0);
    cvt2(v.z, v.w, h1, l1);
    *(uint2*)hp = make_uint2(h0, h1);
    *(uint2*)lp = make_uint2(l0, l1);
}

__global__ __launch_bounds__(256, 3)
void k_all(const float* __restrict__ x, const float* __restrict__ w,
           const int* __restrict__ idx, float* __restrict__ out) {
    extern __shared__ __align__(1024) char sm[];

    int t = threadIdx.x, lane = t & 31;
    int e  = blockIdx.x;
    int n0 = blockIdx.y * TN;

    // ---- phase 0: index dtype detect + ballot compaction (scratch < 1KB) ----
    int* s_list = (int*)sm;          // [128], persists below the ring
    int* s_wcnt = (int*)(sm + 512);
    int* s_flag = (int*)(sm + 552);

    if (t == 0) *s_flag = 0;
    __syncthreads();
    if (t < 128 && idx[2 * t + 1]) atomicOr(s_flag, 1);
    __syncthreads();
    const int is64 = (*s_flag == 0);

    int wid = t >> 5;
    uint32_t bal[8];
    int base = wid * 256;
    {
        int c_w = 0;
#pragma unroll
        for (int j = 0; j < 8; j++) {
            int smp = base + j * 32 + lane;
            int c = is64 ? idx[2 * smp] : idx[smp];
            bal[j] = __ballot_sync(0xffffffffu, c == e);
            c_w += __popc(bal[j]);
        }
        if (lane == 0) s_wcnt[wid] = c_w;
    }
    __syncthreads();
    int woff = 0, cnt = 0;
#pragma unroll
    for (int k = 0; k < 8; k++) {
        int v = s_wcnt[k];
        if (k < wid) woff += v;
        cnt += v;
    }
    {
        int run = woff;
#pragma unroll
        for (int j = 0; j < 8; j++) {
            int smp = base + j * 32 + lane;
            if ((bal[j] >> lane) & 1) {
                int pos = run + __popc(bal[j] & ((1u << lane) - 1));
                if (pos < 128) s_list[pos] = smp;
            }
            run += __popc(bal[j]);
        }
    }
    __syncthreads();          // s_list final; never written again

    if (cnt == 0) return;     // uniform
    int ntiles = (cnt + TM - 1) / TM;
    if (ntiles > 2) ntiles = 2;

    const float* wc = w + (size_t)e * (NOUT * KIN) + (size_t)n0 * KIN;
    const uint32_t sb = smem_u32(sm);

    if (t >= 128) {
        // ================= PRODUCER =================
        int p   = t - 128;
        int rb  = p >> 3;                       // 0..15
        int col = (p & 7) * 4;                  // float col in 32-chunk
        uint32_t so16[4];
#pragma unroll
        for (int j = 0; j < 4; j++)
            so16[j] = SW64((uint32_t)((rb + 16 * j) * 64 + (p & 7) * 8));
        const float* bpp[4];
#pragma unroll
        for (int j = 0; j < 4; j++)
            bpp[j] = wc + (size_t)(rb + 16 * j) * KIN + col;

#pragma unroll 1
        for (int tile = 0; tile < ntiles; tile++) {
            int tb = tile * TM;
            int mcnt = cnt - tb;
            if (mcnt > TM) mcnt = TM;
            const float* app[4];
#pragma unroll
            for (int j = 0; j < 4; j++) {
                int r = rb + 16 * j;
                app[j] = (r < mcnt) ? (x + (size_t)s_list[tb + r] * KIN + col)
                                    : (const float*)0;
            }
            // Prologue: stage-0 loads.
            float4 A[4], B[4];
#pragma unroll
            for (int j = 0; j < 4; j++)
                A[j] = app[j] ? *(const float4*)app[j]
                              : make_float4(0.f, 0.f, 0.f, 0.f);
#pragma unroll
            for (int j = 0; j < 4; j++) B[j] = *(const float4*)bpp[j];

#pragma unroll 1
            for (int s = 0; s < NCH; s++) {
                int sg = tile * NCH + s;
                if (sg >= NSTG) BAR_SYNC(5 + (sg & 3));
                char* stg = sm + RING_OFF + (sg & 3) * STGB;
#pragma unroll
                for (int j = 0; j < 4; j++)
                    cvt_sts(A[j], stg + so16[j], stg + 4096 + so16[j]);
#pragma unroll
                for (int j = 0; j < 4; j++)
                    cvt_sts(B[j], stg + 8192 + so16[j], stg + 12288 + so16[j]);
                // Next-stage loads (overlap with consumer of this stage).
                if (s + 1 < NCH) {
                    int g = (s + 1) * KB;
#pragma unroll
                    for (int j = 0; j < 4; j++)
                        A[j] = app[j] ? *(const float4*)(app[j] + g)
                                      : make_float4(0.f, 0.f, 0.f, 0.f);
#pragma unroll
                    for (int j = 0; j < 4; j++)
                        B[j] = *(const float4*)(bpp[j] + g);
                }
                BAR_ARRIVE(1 + (sg & 3));
            }
        }
    } else {
        // ================= CONSUMER =================
        int cw = t >> 5;                        // 0..3
        int nbase = cw * 16;
        int a_r = (lane & 7) + ((lane >> 3) & 1) * 8;
        int a_c = ((lane >> 4) & 1) * 16;
        int b_r = (lane & 7) + ((lane >> 4) & 1) * 8;
        int b_c = ((lane >> 3) & 1) * 16;

#pragma unroll 1
        for (int tile = 0; tile < ntiles; tile++) {
            int tb = tile * TM;
            int mcnt = cnt - tb;
            if (mcnt > TM) mcnt = TM;
            const int nmf = (mcnt + 15) >> 4;   // 1..4 active 16-row frags

            float acc[4][2][4];
#pragma unroll
            for (int i = 0; i < 4; i++)
#pragma unroll
                for (int j = 0; j < 2; j++)
#pragma unroll
                    for (int q = 0; q < 4; q++) acc[i][j][q] = 0.f;

#pragma unroll 1
            for (int s = 0; s < NCH; s++) {
                int sg = tile * NCH + s;
                BAR_SYNC(1 + (sg & 3));
                uint32_t bs = sb + RING_OFF + (uint32_t)((sg & 3) * STGB);
#pragma unroll
                for (int ks = 0; ks < 2; ks++) {
                    uint32_t bh[4], bl[4];
                    {
                        uint32_t o = SW64((uint32_t)((nbase + b_r) * 64 + ks * 32 + b_c));
                        LDSM4(bh[0], bh[1], bh[2], bh[3], bs + 8192 + o);
                        LDSM4(bl[0], bl[1], bl[2], bl[3], bs + 12288 + o);
                    }
#pragma unroll
                    for (int mf = 0; mf < 4; mf++) {
                        if (mf < nmf) {
                            uint32_t ah[4], al[4];
                            uint32_t o = SW64((uint32_t)((mf * 16 + a_r) * 64 + ks * 32 + a_c));
                            LDSM4(ah[0], ah[1], ah[2], ah[3], bs + o);
                            LDSM4(al[0], al[1], al[2], al[3], bs + 4096 + o);
#pragma unroll
                            for (int nf = 0; nf < 2; nf++) {
                                int oo = nf * 2;
                                MMA(acc[mf][nf], ah, bh[oo], bh[oo + 1]);
                                MMA(acc[mf][nf], ah, bl[oo], bl[oo + 1]);
                                MMA(acc[mf][nf], al, bh[oo], bh[oo + 1]);
                            }
                        }
                    }
                }
                BAR_ARRIVE(5 + (sg & 3));
            }

            // ---- epilogue (s_list persists below ring) ----
#pragma unroll
            for (int mf = 0; mf < 4; mf++) {
                int m0 = mf * 16 + (lane >> 2);
                int m1 = m0 + 8;
                int r0 = (m0 < mcnt) ? s_list[tb + m0] : -1;
                int r1 = (m1 < mcnt) ? s_list[tb + m1] : -1;
#pragma unroll
                for (int nf = 0; nf < 2; nf++) {
                    int col = n0 + nbase + nf * 8 + (lane & 3) * 2;
                    if (r0 >= 0)
                        *(float2*)(out + (size_t)r0 * NOUT + col) =
                            make_float2(acc[mf][nf][0], acc[mf][nf][1]);
                    if (r1 >= 0)
                        *(float2*)(out + (size_t)r1 * NOUT + col) =
                            make_float2(acc[mf][nf][2], acc[mf][nf][3]);
                }
            }
        }
    }
}

extern "C" void kernel_launch(void* const* d_in, const int* in_sizes, int n_in,
                              void* d_out, int out_size) {
    const float* x = 0; const int* idx = 0; const float* w = 0;
    for (int i = 0; i < n_in; i++) {
        if (in_sizes[i] == BB)              idx = (const int*)d_in[i];
        else if (in_sizes[i] == BB * KIN)   x   = (const float*)d_in[i];
        else                                w   = (const float*)d_in[i];
    }
    cudaFuncSetAttribute(k_all, cudaFuncAttributeMaxDynamicSharedMemorySize, SMEM_DYN);
    k_all<<<dim3(CC, NOUT / TN), 256, SMEM_DYN>>>(x, w, idx, (float*)d_out);
}

// round 12
// speedup vs baseline: 1.0656x; 1.0656x over previous
#include <cuda_runtime.h>
#include <cuda_bf16.h>
#include <cstdint>

// SwitchingLinear: out[b,:] = W[idx[b]] @ x[b]
// B=2048, C=64, IN=OUT=512 fp32.
// ONE fused kernel. cp.async fp32 ring (5 slots, 4-stage lookahead) feeds
// 8 symmetric compute warps that build split-bf16 MMA fragments directly
// from fp32 smem (LDS.64 + cvt2) -- no producer warps, no bf16 smem.
// Split-bf16: v = hi + lo;  D = Ah*Bh + Ah*Bl + Al*Bh (fp32 accum).
// Warp = (m-half 32) x (n-quarter 32).  16-row M-skip.
// Grid = (expert, n-block 128): 256 CTAs.

#define BB    2048
#define CC    64
#define KIN   512
#define NOUT  512
#define TM    64
#define TN    128
#define KB    16
#define NCH   (KIN / KB)     // 32
#define NSTG  5
#define PAD   96             // bytes per 16-float row (64B data + 32B pad)
#define A_OFF 0
#define B_OFF (64 * PAD)     // 6144
#define STGB  (192 * PAD)    // 18432 = A(64 rows) + B(128 rows)
#define RING_OFF 1024
#define SMEM_DYN (RING_OFF + NSTG * STGB)   // 93184

__device__ __forceinline__ uint32_t smem_u32(const void* p) {
    uint32_t a;
    asm("{ .reg .u64 t; cvta.to.shared.u64 t, %1; cvt.u32.u64 %0, t; }"
        : "=r"(a) : "l"(p));
    return a;
}

#define CP16(dst, src, sz)                                                   \
    asm volatile("cp.async.cg.shared.global [%0], [%1], 16, %2;"             \
                 :: "r"(dst), "l"(src), "r"(sz))
#define CP_COMMIT() asm volatile("cp.async.commit_group;" ::: "memory")
#define CP_WAIT3()  asm volatile("cp.async.wait_group 3;"  ::: "memory")

#define LDS64(f0, f1, a)                                                     \
    asm volatile("ld.shared.v2.f32 {%0,%1}, [%2];"                           \
                 : "=f"(f0), "=f"(f1) : "r"(a))

#define MMA(d, a, b0, b1)                                                    \
    asm volatile("mma.sync.aligned.m16n8k16.row.col.f32.bf16.bf16.f32 "      \
                 "{%0,%1,%2,%3},{%4,%5,%6,%7},{%8,%9},{%0,%1,%2,%3};"        \
                 : "+f"((d)[0]), "+f"((d)[1]), "+f"((d)[2]), "+f"((d)[3])    \
                 : "r"((a)[0]), "r"((a)[1]), "r"((a)[2]), "r"((a)[3]),       \
                   "r"(b0), "r"(b1))

// Split fp32 pair -> bf16x2 hi + bf16x2 lo (lo = v - float(hi)).
__device__ __forceinline__ void cvt2(float f0, float f1, uint32_t& h, uint32_t& l) {
    asm("cvt.rn.bf16x2.f32 %0, %1, %2;" : "=r"(h) : "f"(f1), "f"(f0));
    float h0 = __uint_as_float(h << 16);
    float h1 = __uint_as_float(h & 0xFFFF0000u);
    float l0 = f0 - h0, l1 = f1 - h1;
    asm("cvt.rn.bf16x2.f32 %0, %1, %2;" : "=r"(l) : "f"(l1), "f"(l0));
}

__global__ __launch_bounds__(256, 2)
void k_all(const float* __restrict__ x, const float* __restrict__ w,
           const int* __restrict__ idx, float* __restrict__ out) {
    extern __shared__ __align__(1024) char sm[];

    int t = threadIdx.x, lane = t & 31, wid = t >> 5;
    int e  = blockIdx.x;
    int n0 = blockIdx.y * TN;

    // ---- phase 0: index dtype detect + ballot compaction ----
    int* s_list = (int*)sm;          // [128], persists below the ring
    int* s_wcnt = (int*)(sm + 512);
    int* s_flag = (int*)(sm + 552);

    if (t == 0) *s_flag = 0;
    __syncthreads();
    if (t < 128 && idx[2 * t + 1]) atomicOr(s_flag, 1);
    __syncthreads();
    const int is64 = (*s_flag == 0);

    uint32_t bal[8];
    int base = wid * 256;
    {
        int c_w = 0;
#pragma unroll
        for (int j = 0; j < 8; j++) {
            int smp = base + j * 32 + lane;
            int c = is64 ? idx[2 * smp] : idx[smp];
            bal[j] = __ballot_sync(0xffffffffu, c == e);
            c_w += __popc(bal[j]);
        }
        if (lane == 0) s_wcnt[wid] = c_w;
    }
    __syncthreads();
    int woff = 0, cnt = 0;
#pragma unroll
    for (int k = 0; k < 8; k++) {
        int v = s_wcnt[k];
        if (k < wid) woff += v;
        cnt += v;
    }
    {
        int run = woff;
#pragma unroll
        for (int j = 0; j < 8; j++) {
            int smp = base + j * 32 + lane;
            if ((bal[j] >> lane) & 1) {
                int pos = run + __popc(bal[j] & ((1u << lane) - 1));
                if (pos < 128) s_list[pos] = smp;
            }
            run += __popc(bal[j]);
        }
    }
    __syncthreads();          // s_list final

    if (cnt == 0) return;     // uniform
    int ntiles = (cnt + TM - 1) / TM;
    if (ntiles > 2) ntiles = 2;

    const float* wc = w + (size_t)e * (NOUT * KIN) + (size_t)n0 * KIN;
    const uint32_t sb = smem_u32(sm) + RING_OFF;

    // Copy-task mapping (per thread): A row ra=t>>2 chunk ca=t&3;
    // B rows ra, ra+64, same chunk.
    const int ra = t >> 2, ca = t & 3;
    const float* bsrc0 = wc + (size_t)ra * KIN + ca * 4;
    const float* bsrc1 = bsrc0 + (size_t)64 * KIN;
    const uint32_t dA  = (uint32_t)(A_OFF + ra * PAD + ca * 16);
    const uint32_t dB0 = (uint32_t)(B_OFF + ra * PAD + ca * 16);
    const uint32_t dB1 = dB0 + (uint32_t)(64 * PAD);

    // Warp tile: m-half wm (0/1), n-quarter wn (0..3).
    const int wm = wid >> 2, wn = wid & 3;
    const int g = lane >> 2, tt = lane & 3;

#pragma unroll 1
    for (int tile = 0; tile < ntiles; tile++) {
        int tb = tile * TM;
        int mcnt = cnt - tb;
        if (mcnt > TM) mcnt = TM;
        const int nmf = (mcnt + 15) >> 4;

        const float* asrc = (ra < mcnt)
            ? (x + (size_t)s_list[tb + ra] * KIN + ca * 4) : x;
        const uint32_t asz = (ra < mcnt) ? 16u : 0u;

        // Prologue: issue stages 0..3.
#pragma unroll
        for (int s = 0; s < NSTG - 1; s++) {
            uint32_t sl = sb + (uint32_t)(s % NSTG) * STGB;
            int k0 = s * KB;
            CP16(sl + dA, asrc + k0, asz);
            CP16(sl + dB0, bsrc0 + k0, 16u);
            CP16(sl + dB1, bsrc1 + k0, 16u);
            CP_COMMIT();
        }

        float acc[2][4][4];
#pragma unroll
        for (int i = 0; i < 2; i++)
#pragma unroll
            for (int j = 0; j < 4; j++)
#pragma unroll
                for (int q = 0; q < 4; q++) acc[i][j][q] = 0.f;

#pragma unroll 1
        for (int s = 0; s < NCH; s++) {
            CP_WAIT3();
            __syncthreads();
            uint32_t sl = sb + (uint32_t)(s % NSTG) * STGB;

            // Build B fragments (4 n8 blocks) hi+lo.
            uint32_t bh[4][2], bl[4][2];
#pragma unroll
            for (int p = 0; p < 4; p++) {
                uint32_t ad = sl + B_OFF + (uint32_t)((wn * 32 + p * 8 + g) * PAD + tt * 8);
                float f0, f1;
                LDS64(f0, f1, ad);
                cvt2(f0, f1, bh[p][0], bl[p][0]);
                LDS64(f0, f1, ad + 32);
                cvt2(f0, f1, bh[p][1], bl[p][1]);
            }

            // A fragments + MMAs per active m-frag.
#pragma unroll
            for (int i = 0; i < 2; i++) {
                int mf = wm * 2 + i;
                if (mf < nmf) {
                    uint32_t ah[4], al[4];
                    uint32_t ad = sl + (uint32_t)((mf * 16 + g) * PAD + tt * 8);
                    float f0, f1;
                    LDS64(f0, f1, ad);                 cvt2(f0, f1, ah[0], al[0]);
                    LDS64(f0, f1, ad + 8 * PAD);       cvt2(f0, f1, ah[1], al[1]);
                    LDS64(f0, f1, ad + 32);            cvt2(f0, f1, ah[2], al[2]);
                    LDS64(f0, f1, ad + 8 * PAD + 32);  cvt2(f0, f1, ah[3], al[3]);
#pragma unroll
                    for (int p = 0; p < 4; p++) {
                        MMA(acc[i][p], ah, bh[p][0], bh[p][1]);
                        MMA(acc[i][p], ah, bl[p][0], bl[p][1]);
                        MMA(acc[i][p], al, bh[p][0], bh[p][1]);
                    }
                }
            }
            __syncthreads();

            // Issue stage s+4.
            if (s + NSTG - 1 < NCH) {
                int k0 = (s + NSTG - 1) * KB;
                uint32_t sn = sb + (uint32_t)((s + NSTG - 1) % NSTG) * STGB;
                CP16(sn + dA, asrc + k0, asz);
                CP16(sn + dB0, bsrc0 + k0, 16u);
                CP16(sn + dB1, bsrc1 + k0, 16u);
            }
            CP_COMMIT();
        }

        // ---- epilogue ----
#pragma unroll
        for (int i = 0; i < 2; i++) {
            int mf = wm * 2 + i;
            int m0 = mf * 16 + g;
            int m1 = m0 + 8;
            int r0 = (m0 < mcnt) ? s_list[tb + m0] : -1;
            int r1 = (m1 < mcnt) ? s_list[tb + m1] : -1;
#pragma unroll
            for (int p = 0; p < 4; p++) {
                int col = n0 + wn * 32 + p * 8 + tt * 2;
                if (r0 >= 0)
                    *(float2*)(out + (size_t)r0 * NOUT + col) =
                        make_float2(acc[i][p][0], acc[i][p][1]);
                if (r1 >= 0)
                    *(float2*)(out + (size_t)r1 * NOUT + col) =
                        make_float2(acc[i][p][2], acc[i][p][3]);
            }
        }
        if (tile + 1 < ntiles) {
            asm volatile("cp.async.wait_group 0;" ::: "memory");
            __syncthreads();
        }
    }
}

extern "C" void kernel_launch(void* const* d_in, const int* in_sizes, int n_in,
                              void* d_out, int out_size) {
    const float* x = 0; const int* idx = 0; const float* w = 0;
    for (int i = 0; i < n_in; i++) {
        if (in_sizes[i] == BB)              idx = (const int*)d_in[i];
        else if (in_sizes[i] == BB * KIN)   x   = (const float*)d_in[i];
        else                                w   = (const float*)d_in[i];
    }
    cudaFuncSetAttribute(k_all, cudaFuncAttributeMaxDynamicSharedMemorySize, SMEM_DYN);
    k_all<<<dim3(CC, NOUT / TN), 256, SMEM_DYN>>>(x, w, idx, (float*)d_out);
}

// round 13
// speedup vs baseline: 1.7568x; 1.6486x over previous
#include <cuda_runtime.h>
#include <cuda_fp16.h>
#include <cstdint>

// SwitchingLinear: out[b,:] = W[idx[b]] @ x[b]
// B=2048, C=64, IN=OUT=512 fp32.
// ONE fused kernel, warp-specialized producer/consumer, 4-deep ring.
// SINGLE-TERM fp16 HMMA (rel_err budget 1e-3; fp16 rn gives ~3e-4):
//   warps 4-7: producers (LDG fp32 -> cvt.rn.f16x2 -> STS.128)
//   warps 0-3: consumers (LDSM -> m16n8k16 f16 MMA, fp32 accum), M-skip
// KB=64 (8 stages): halves barrier/fixed costs vs KB=32.
// Grid = (expert, n-block 128): 256 CTAs.

#define BB    2048
#define CC    64
#define KIN   512
#define NOUT  512
#define TM    64
#define TN    128
#define KB    64
#define NCH   (KIN / KB)     // 8
#define NSTG  4
#define STGB  24576          // A 64x128B | B 128x128B
#define RING_OFF 1024
#define SMEM_DYN (RING_OFF + NSTG * STGB)   // 99328

__device__ __forceinline__ uint32_t smem_u32(const void* p) {
    uint32_t a;
    asm("{ .reg .u64 t; cvta.to.shared.u64 t, %1; cvt.u32.u64 %0, t; }"
        : "=r"(a) : "l"(p));
    return a;
}

#define SW128(o) ((o) ^ (((o) >> 3) & 0x70))

#define BAR_SYNC(id)   asm volatile("bar.sync %0, 256;"   :: "r"(id) : "memory")
#define BAR_ARRIVE(id) asm volatile("bar.arrive %0, 256;" :: "r"(id) : "memory")

#define LDSM4(r0, r1, r2, r3, a)                                             \
    asm volatile("ldmatrix.sync.aligned.m8n8.x4.shared.b16 {%0,%1,%2,%3}, [%4];" \
                 : "=r"(r0), "=r"(r1), "=r"(r2), "=r"(r3) : "r"(a))

#define MMA(d, a, b0, b1)                                                    \
    asm volatile("mma.sync.aligned.m16n8k16.row.col.f32.f16.f16.f32 "        \
                 "{%0,%1,%2,%3},{%4,%5,%6,%7},{%8,%9},{%0,%1,%2,%3};"        \
                 : "+f"((d)[0]), "+f"((d)[1]), "+f"((d)[2]), "+f"((d)[3])    \
                 : "r"((a)[0]), "r"((a)[1]), "r"((a)[2]), "r"((a)[3]),       \
                   "r"(b0), "r"(b1))

// 8 fp32 -> 8 fp16 (round-nearest), packed uint4.
__device__ __forceinline__ uint4 cvt8(const float4& u, const float4& v) {
    uint4 r;
    asm("cvt.rn.f16x2.f32 %0, %1, %2;" : "=r"(r.x) : "f"(u.y), "f"(u.x));
    asm("cvt.rn.f16x2.f32 %0, %1, %2;" : "=r"(r.y) : "f"(u.w), "f"(u.z));
    asm("cvt.rn.f16x2.f32 %0, %1, %2;" : "=r"(r.z) : "f"(v.y), "f"(v.x));
    asm("cvt.rn.f16x2.f32 %0, %1, %2;" : "=r"(r.w) : "f"(v.w), "f"(v.z));
    return r;
}

__global__ __launch_bounds__(256, 2)
void k_all(const float* __restrict__ x, const float* __restrict__ w,
           const int* __restrict__ idx, float* __restrict__ out) {
    extern __shared__ __align__(1024) char sm[];

    int t = threadIdx.x, lane = t & 31, wid = t >> 5;
    int e  = blockIdx.x;
    int n0 = blockIdx.y * TN;

    // ---- phase 0: index dtype detect + ballot compaction ----
    int* s_list = (int*)sm;          // [128], persists below the ring
    int* s_wcnt = (int*)(sm + 512);
    int* s_flag = (int*)(sm + 552);

    if (t == 0) *s_flag = 0;
    __syncthreads();
    if (t < 128 && idx[2 * t + 1]) atomicOr(s_flag, 1);
    __syncthreads();
    const int is64 = (*s_flag == 0);

    uint32_t bal[8];
    int base = wid * 256;
    {
        int c_w = 0;
#pragma unroll
        for (int j = 0; j < 8; j++) {
            int smp = base + j * 32 + lane;
            int c = is64 ? idx[2 * smp] : idx[smp];
            bal[j] = __ballot_sync(0xffffffffu, c == e);
            c_w += __popc(bal[j]);
        }
        if (lane == 0) s_wcnt[wid] = c_w;
    }
    __syncthreads();
    int woff = 0, cnt = 0;
#pragma unroll
    for (int k = 0; k < 8; k++) {
        int v = s_wcnt[k];
        if (k < wid) woff += v;
        cnt += v;
    }
    {
        int run = woff;
#pragma unroll
        for (int j = 0; j < 8; j++) {
            int smp = base + j * 32 + lane;
            if ((bal[j] >> lane) & 1) {
                int pos = run + __popc(bal[j] & ((1u << lane) - 1));
                if (pos < 128) s_list[pos] = smp;
            }
            run += __popc(bal[j]);
        }
    }
    __syncthreads();          // s_list final

    if (cnt == 0) return;     // uniform
    int ntiles = (cnt + TM - 1) / TM;
    if (ntiles > 2) ntiles = 2;

    const float* wc = w + (size_t)e * (NOUT * KIN) + (size_t)n0 * KIN;
    const uint32_t sb = smem_u32(sm) + RING_OFF;

    if (t >= 128) {
        // ================= PRODUCER =================
        int p  = t - 128;
        int rg = p >> 3;                 // 0..15 row group
        int kl = (p & 7) * 8;            // float col 0..56 within 64-chunk
        uint32_t so[8];
#pragma unroll
        for (int j = 0; j < 8; j++)      // byte chunk for row rg+16j
            so[j] = SW128((uint32_t)((rg + 16 * j) * 128 + kl * 2));
        const float* bpp[8];
#pragma unroll
        for (int j = 0; j < 8; j++)
            bpp[j] = wc + (size_t)(rg + 16 * j) * KIN + kl;

#pragma unroll 1
        for (int tile = 0; tile < ntiles; tile++) {
            int tb = tile * TM;
            int mcnt = cnt - tb;
            if (mcnt > TM) mcnt = TM;
            const float* app[4];
#pragma unroll
            for (int j = 0; j < 4; j++) {
                int r = rg + 16 * j;
                app[j] = (r < mcnt) ? (x + (size_t)s_list[tb + r] * KIN + kl)
                                    : (const float*)0;
            }

#pragma unroll 1
            for (int s = 0; s < NCH; s++) {
                int sg = tile * NCH + s;
                int k0 = s * KB;
                // Issue all loads up-front (MLP ~24), then wait-empty.
                float4 a0[4], a1[4];
#pragma unroll
                for (int j = 0; j < 4; j++) {
                    if (app[j]) {
                        a0[j] = *(const float4*)(app[j] + k0);
                        a1[j] = *(const float4*)(app[j] + k0 + 4);
                    } else {
                        a0[j] = make_float4(0.f, 0.f, 0.f, 0.f);
                        a1[j] = a0[j];
                    }
                }
                float4 b0[8], b1[8];
#pragma unroll
                for (int j = 0; j < 8; j++) {
                    b0[j] = *(const float4*)(bpp[j] + k0);
                    b1[j] = *(const float4*)(bpp[j] + k0 + 4);
                }
                if (sg >= NSTG) BAR_SYNC(5 + (sg & 3));
                char* stg = sm + RING_OFF + (sg & 3) * STGB;
#pragma unroll
                for (int j = 0; j < 4; j++)
                    *(uint4*)(stg + so[j]) = cvt8(a0[j], a1[j]);
#pragma unroll
                for (int j = 0; j < 8; j++)
                    *(uint4*)(stg + 8192 + so[j]) = cvt8(b0[j], b1[j]);
                BAR_ARRIVE(1 + (sg & 3));
            }
        }
    } else {
        // ================= CONSUMER =================
        int cw = wid;                    // 0..3
        int nbase = cw * 32;
        int a_r = (lane & 7) + ((lane >> 3) & 1) * 8;
        int a_c = ((lane >> 4) & 1) * 16;   // bytes (k half)
        int b_r = (lane & 7) + ((lane >> 4) & 1) * 8;
        int b_c = ((lane >> 3) & 1) * 16;   // bytes

#pragma unroll 1
        for (int tile = 0; tile < ntiles; tile++) {
            int tb = tile * TM;
            int mcnt = cnt - tb;
            if (mcnt > TM) mcnt = TM;
            const int nmf = (mcnt + 15) >> 4;   // 1..4

            float acc[4][4][4];
#pragma unroll
            for (int i = 0; i < 4; i++)
#pragma unroll
                for (int j = 0; j < 4; j++)
#pragma unroll
                    for (int q = 0; q < 4; q++) acc[i][j][q] = 0.f;

#pragma unroll 1
            for (int s = 0; s < NCH; s++) {
                int sg = tile * NCH + s;
                BAR_SYNC(1 + (sg & 3));
                uint32_t bs = sb + (uint32_t)((sg & 3) * STGB);
#pragma unroll
                for (int ks = 0; ks < 4; ks++) {     // 4 x k16 per stage
                    uint32_t bh[2][4];
#pragma unroll
                    for (int np = 0; np < 2; np++) {
                        uint32_t o = SW128((uint32_t)((nbase + np * 16 + b_r) * 128 + ks * 32 + b_c));
                        LDSM4(bh[np][0], bh[np][1], bh[np][2], bh[np][3], bs + 8192 + o);
                    }
#pragma unroll
                    for (int mf = 0; mf < 4; mf++) {
                        if (mf < nmf) {
                            uint32_t ah[4];
                            uint32_t o = SW128((uint32_t)((mf * 16 + a_r) * 128 + ks * 32 + a_c));
                            LDSM4(ah[0], ah[1], ah[2], ah[3], bs + o);
#pragma unroll
                            for (int nf = 0; nf < 4; nf++) {
                                int np = nf >> 1, oo = (nf & 1) * 2;
                                MMA(acc[mf][nf], ah, bh[np][oo], bh[np][oo + 1]);
                            }
                        }
                    }
                }
                BAR_ARRIVE(5 + (sg & 3));
            }

            // ---- epilogue ----
#pragma unroll
            for (int mf = 0; mf < 4; mf++) {
                int m0 = mf * 16 + (lane >> 2);
                int m1 = m0 + 8;
                int r0 = (m0 < mcnt) ? s_list[tb + m0] : -1;
                int r1 = (m1 < mcnt) ? s_list[tb + m1] : -1;
#pragma unroll
                for (int nf = 0; nf < 4; nf++) {
                    int col = n0 + nbase + nf * 8 + (lane & 3) * 2;
                    if (r0 >= 0)
                        *(float2*)(out + (size_t)r0 * NOUT + col) =
                            make_float2(acc[mf][nf][0], acc[mf][nf][1]);
                    if (r1 >= 0)
                        *(float2*)(out + (size_t)r1 * NOUT + col) =
                            make_float2(acc[mf][nf][2], acc[mf][nf][3]);
                }
            }
        }
    }
}

extern "C" void kernel_launch(void* const* d_in, const int* in_sizes, int n_in,
                              void* d_out, int out_size) {
    const float* x = 0; const int* idx = 0; const float* w = 0;
    for (int i = 0; i < n_in; i++) {
        if (in_sizes[i] == BB)              idx = (const int*)d_in[i];
        else if (in_sizes[i] == BB * KIN)   x   = (const float*)d_in[i];
        else                                w   = (const float*)d_in[i];
    }
    cudaFuncSetAttribute(k_all, cudaFuncAttributeMaxDynamicSharedMemorySize, SMEM_DYN);
    k_all<<<dim3(CC, NOUT / TN), 256, SMEM_DYN>>>(x, w, idx, (float*)d_out);
}